// round 1
// baseline (speedup 1.0000x reference)
#include <cuda_runtime.h>
#include <cuda_bf16.h>
#include <math.h>

#define VOCAB 32000
#define DMODEL 256
#define NREP 16
#define NLAYER 6
#define DS 16
#define DC 4
#define DI 512
#define DTR 16
#define NH 4
#define HD 64
#define LSEQ 128
#define ROWS (NREP*LSEQ)   // 2048

// ---------------- scratch (device globals; no allocation allowed) ----------
__device__ float g_h[ROWS*DMODEL];        // residual stream [n*128+l, 256]
__device__ float g_xn[ROWS*DMODEL];       // ln1 out
__device__ float g_xz[ROWS*2*DI];         // in_proj out [2048,1024]
__device__ float g_u[ROWS*DI];            // conv+silu out
__device__ float g_xdbl[ROWS*(DTR+2*DS)]; // [2048,48]
__device__ float g_dt[ROWS*DI];           // softplus(dt)
__device__ float g_y[ROWS*DI];            // scan out + skip
__device__ float g_gate[ROWS*DI];         // y * silu(z)
__device__ float g_xc[ROWS*DMODEL];       // ln2 out, permuted rows l*16+n
__device__ float g_qkv[ROWS*3*DMODEL];    // [2048,768] rows l*16+n
__device__ float g_attno[ROWS*DMODEL];    // attention o (pre out-proj)
__device__ float g_co[ROWS*DMODEL];       // attn_out gemm result
__device__ float g_hm[LSEQ*DMODEL];       // replica mean
__device__ float g_hf[LSEQ*DMODEL];       // final LN

// ---------------- helpers ----------
__device__ __forceinline__ float siluf(float x) {
    return x / (1.f + __expf(-x));
}

__device__ float blockReduceSum256(float v) {
    __shared__ float s[8];
    __shared__ float tot;
    int lane = threadIdx.x & 31, wid = threadIdx.x >> 5;
    #pragma unroll
    for (int o = 16; o > 0; o >>= 1) v += __shfl_xor_sync(0xffffffffu, v, o);
    if (lane == 0) s[wid] = v;
    __syncthreads();
    if (wid == 0) {
        float w = (lane < 8) ? s[lane] : 0.f;
        #pragma unroll
        for (int o = 4; o > 0; o >>= 1) w += __shfl_xor_sync(0xffffffffu, w, o);
        if (lane == 0) tot = w;
    }
    __syncthreads();
    float r = tot;
    __syncthreads();   // allow re-use of s[] by a following call
    return r;
}

// ---------------- kernels ----------

// h[n,l,:] = embedding[x[l],:]
__global__ void k_embed(const int* __restrict__ x, const float* __restrict__ emb) {
    int idx = blockIdx.x * blockDim.x + threadIdx.x;       // 16*128*256
    if (idx >= ROWS*DMODEL) return;
    int d = idx & (DMODEL-1);
    int r = idx >> 8;           // n*128+l
    int l = r & (LSEQ-1);
    g_h[idx] = emb[(size_t)x[l]*DMODEL + d];
}

// LayerNorm over 256. grid = nrows, block = 256.
// permuted: write out[(l*16+n)*256+d] from row r=n*128+l
__global__ void k_ln(const float* __restrict__ in, const float* __restrict__ w,
                     const float* __restrict__ b, float* __restrict__ out, int permuted) {
    int r = blockIdx.x;
    int d = threadIdx.x;
    float v = in[(size_t)r*DMODEL + d];
    float m = blockReduceSum256(v) * (1.f/DMODEL);
    float c = v - m;
    float var = blockReduceSum256(c*c) * (1.f/DMODEL);
    float res = c * rsqrtf(var + 1e-5f) * w[d] + b[d];
    if (permuted) {
        int n = r >> 7, l = r & (LSEQ-1);
        out[(size_t)((l<<4)+n)*DMODEL + d] = res;
    } else {
        out[(size_t)r*DMODEL + d] = res;
    }
}

// C[M,N] = act(A[M,K] @ W[N,K]^T + bias)   (optionally += into C)
#define BM 64
#define BN 64
#define BK 16
__global__ void k_gemm(const float* __restrict__ A, int lda,
                       const float* __restrict__ W, int ldw,
                       const float* __restrict__ bias,
                       float* __restrict__ C, int ldc,
                       int M, int N, int K, int act, int acc) {
    __shared__ float As[BK][BM+1];
    __shared__ float Ws[BK][BN+1];
    int tid = threadIdx.x;
    int m0 = blockIdx.y * BM;
    int n0 = blockIdx.x * BN;
    int tx = tid & 15, ty = tid >> 4;
    float accr[4][4] = {};
    for (int k0 = 0; k0 < K; k0 += BK) {
        #pragma unroll
        for (int i = 0; i < 4; i++) {
            int idx = tid + i*256;
            int m = idx >> 4;
            int k = idx & 15;
            int gm = m0 + m, gk = k0 + k;
            As[k][m] = (gm < M && gk < K) ? A[(size_t)gm*lda + gk] : 0.f;
            int gn = n0 + m;
            Ws[k][m] = (gn < N && gk < K) ? W[(size_t)gn*ldw + gk] : 0.f;
        }
        __syncthreads();
        #pragma unroll
        for (int k = 0; k < BK; k++) {
            float a[4], w[4];
            #pragma unroll
            for (int i = 0; i < 4; i++) a[i] = As[k][ty*4+i];
            #pragma unroll
            for (int j = 0; j < 4; j++) w[j] = Ws[k][tx*4+j];
            #pragma unroll
            for (int i = 0; i < 4; i++)
                #pragma unroll
                for (int j = 0; j < 4; j++)
                    accr[i][j] += a[i]*w[j];
        }
        __syncthreads();
    }
    #pragma unroll
    for (int i = 0; i < 4; i++) {
        int gm = m0 + ty*4 + i;
        if (gm >= M) continue;
        #pragma unroll
        for (int j = 0; j < 4; j++) {
            int gn = n0 + tx*4 + j;
            if (gn >= N) continue;
            float v = accr[i][j];
            if (bias) v += bias[gn];
            if (act == 1) v = (v > 20.f) ? v : log1pf(expf(v));   // softplus
            size_t o = (size_t)gm*ldc + gn;
            if (acc) C[o] += v; else C[o] = v;
        }
    }
}

// causal depthwise conv (DC=4) + bias + silu.  u in = xz[:, :512] (ld 1024)
__global__ void k_conv(const float* __restrict__ cw, const float* __restrict__ cb) {
    int idx = blockIdx.x * blockDim.x + threadIdx.x;   // 2048*512
    if (idx >= ROWS*DI) return;
    int c = idx & (DI-1);
    int r = idx >> 9;
    int t = r & (LSEQ-1);
    int b = r >> 7;
    float acc = cb[c];
    #pragma unroll
    for (int k = 0; k < DC; k++) {
        int tt = t - (DC-1) + k;
        if (tt >= 0) acc += g_xz[(size_t)((b<<7)+tt)*(2*DI) + c] * cw[c*DC + k];
    }
    g_u[idx] = siluf(acc);
}

// selective scan. grid (8 dchunks, 16 batches), block 1024: tid = s + 16*dl
__global__ void k_scan(const float* __restrict__ A_log, const float* __restrict__ skipD) {
    __shared__ float sdt[64], su[64], sB[DS], sC[DS];
    int b = blockIdx.y;
    int dchunk = blockIdx.x;
    int tid = threadIdx.x;
    int s = tid & 15;
    int dl = tid >> 4;             // 0..63
    int d = dchunk*64 + dl;
    float Ads = -__expf(A_log[d*DS + s]);
    float skip = skipD[d];
    float hstate = 0.f;
    for (int t = 0; t < LSEQ; t++) {
        int row = (b<<7) + t;
        if (tid < 64)                      sdt[tid]      = g_dt[(size_t)row*DI + dchunk*64 + tid];
        else if (tid < 128)                su[tid-64]    = g_u [(size_t)row*DI + dchunk*64 + (tid-64)];
        else if (tid < 128+DS)             sB[tid-128]   = g_xdbl[(size_t)row*48 + DTR + (tid-128)];
        else if (tid < 128+2*DS)           sC[tid-128-DS]= g_xdbl[(size_t)row*48 + DTR + DS + (tid-128-DS)];
        __syncthreads();
        float dtv = sdt[dl];
        float uv  = su[dl];
        hstate = __expf(dtv * Ads) * hstate + dtv * uv * sB[s];
        float p = hstate * sC[s];
        #pragma unroll
        for (int m = 8; m >= 1; m >>= 1) p += __shfl_xor_sync(0xffffffffu, p, m, 16);
        if (s == 0) g_y[(size_t)row*DI + d] = p + uv * skip;
        __syncthreads();
    }
}

// gate = y * silu(z),  z = xz[:, 512:]
__global__ void k_gate() {
    int idx = blockIdx.x * blockDim.x + threadIdx.x;
    if (idx >= ROWS*DI) return;
    int d = idx & (DI-1);
    int r = idx >> 9;
    float z = g_xz[(size_t)r*(2*DI) + DI + d];
    g_gate[idx] = g_y[idx] * siluf(z);
}

// attention over the 16 replicas at each position l. grid=128, block=256.
__global__ void k_attn() {
    __shared__ float sK[NREP][DMODEL];   // 16KB
    __shared__ float sV[NREP][DMODEL];   // 16KB
    __shared__ float sS[NH][NREP][NREP]; // 4KB
    int l = blockIdx.x;
    int tid = threadIdx.x;
    // preload K,V
    for (int idx = tid; idx < NREP*DMODEL; idx += 256) {
        int n = idx >> 8, d = idx & (DMODEL-1);
        size_t base = (size_t)((l<<4)+n)*(3*DMODEL);
        sK[n][d] = g_qkv[base + DMODEL + d];
        sV[n][d] = g_qkv[base + 2*DMODEL + d];
    }
    __syncthreads();
    // scores
    for (int idx = tid; idx < NH*NREP*NREP; idx += 256) {
        int h = idx >> 8;
        int i = (idx >> 4) & 15;
        int j = idx & 15;
        const float* q = &g_qkv[(size_t)((l<<4)+i)*(3*DMODEL) + h*HD];
        float dot = 0.f;
        #pragma unroll 8
        for (int dh = 0; dh < HD; dh++) dot += q[dh] * sK[j][h*HD + dh];
        sS[h][i][j] = dot * 0.125f;   // 1/sqrt(64)
    }
    __syncthreads();
    // softmax over j (64 rows)
    if (tid < NH*NREP) {
        int h = tid >> 4, i = tid & 15;
        float mx = -1e30f;
        #pragma unroll
        for (int j = 0; j < NREP; j++) mx = fmaxf(mx, sS[h][i][j]);
        float sum = 0.f;
        #pragma unroll
        for (int j = 0; j < NREP; j++) { float e = __expf(sS[h][i][j]-mx); sS[h][i][j] = e; sum += e; }
        float inv = 1.f/sum;
        #pragma unroll
        for (int j = 0; j < NREP; j++) sS[h][i][j] *= inv;
    }
    __syncthreads();
    // o = att @ v
    for (int idx = tid; idx < NREP*DMODEL; idx += 256) {
        int i = idx >> 8, d = idx & (DMODEL-1);
        int h = d >> 6;
        float o = 0.f;
        #pragma unroll
        for (int j = 0; j < NREP; j++) o += sS[h][i][j] * sV[j][d];
        g_attno[(size_t)((l<<4)+i)*DMODEL + d] = o;
    }
}

// h[n,l,:] += co[l*16+n,:]
__global__ void k_scatter_add() {
    int idx = blockIdx.x * blockDim.x + threadIdx.x;   // 2048*256
    if (idx >= ROWS*DMODEL) return;
    int d = idx & (DMODEL-1);
    int r = idx >> 8;                   // l*16+n
    int l = r >> 4, n = r & 15;
    g_h[(size_t)((n<<7)+l)*DMODEL + d] += g_co[idx];
}

// hm[l,d] = mean_n h[n,l,d]
__global__ void k_mean() {
    int idx = blockIdx.x * blockDim.x + threadIdx.x;   // 128*256
    if (idx >= LSEQ*DMODEL) return;
    int d = idx & (DMODEL-1);
    int l = idx >> 8;
    float s = 0.f;
    #pragma unroll
    for (int n = 0; n < NREP; n++) s += g_h[(size_t)((n<<7)+l)*DMODEL + d];
    g_hm[idx] = s * (1.f/NREP);
}

// ---------------- launch ----------
extern "C" void kernel_launch(void* const* d_in, const int* in_sizes, int n_in,
                              void* d_out, int out_size) {
    const int*   x        = (const int*)  d_in[0];
    const float* emb      = (const float*)d_in[1];
    const float* n1w      = (const float*)d_in[2];
    const float* n1b      = (const float*)d_in[3];
    const float* n2w      = (const float*)d_in[4];
    const float* n2b      = (const float*)d_in[5];
    const float* ipw      = (const float*)d_in[6];
    const float* cw       = (const float*)d_in[7];
    const float* cb       = (const float*)d_in[8];
    const float* xpw      = (const float*)d_in[9];
    const float* dpw      = (const float*)d_in[10];
    const float* dpb      = (const float*)d_in[11];
    const float* alog     = (const float*)d_in[12];
    const float* dskip    = (const float*)d_in[13];
    const float* opw      = (const float*)d_in[14];
    const float* aiw      = (const float*)d_in[15];
    const float* aib      = (const float*)d_in[16];
    const float* aow      = (const float*)d_in[17];
    const float* aob      = (const float*)d_in[18];
    const float* nfw      = (const float*)d_in[19];
    const float* nfb      = (const float*)d_in[20];
    const float* headb    = (const float*)d_in[21];
    float* out = (float*)d_out;

    float* ph; cudaGetSymbolAddress((void**)&ph, g_h);
    float* pxn; cudaGetSymbolAddress((void**)&pxn, g_xn);
    float* pxz; cudaGetSymbolAddress((void**)&pxz, g_xz);
    float* pu; cudaGetSymbolAddress((void**)&pu, g_u);
    float* pxdbl; cudaGetSymbolAddress((void**)&pxdbl, g_xdbl);
    float* pdt; cudaGetSymbolAddress((void**)&pdt, g_dt);
    float* pgate; cudaGetSymbolAddress((void**)&pgate, g_gate);
    float* pxc; cudaGetSymbolAddress((void**)&pxc, g_xc);
    float* pqkv; cudaGetSymbolAddress((void**)&pqkv, g_qkv);
    float* pattno; cudaGetSymbolAddress((void**)&pattno, g_attno);
    float* pco; cudaGetSymbolAddress((void**)&pco, g_co);
    float* phm; cudaGetSymbolAddress((void**)&phm, g_hm);
    float* phf; cudaGetSymbolAddress((void**)&phf, g_hf);

    // embed
    k_embed<<<(ROWS*DMODEL+255)/256, 256>>>(x, emb);

    for (int i = 0; i < NLAYER; i++) {
        const float* L_n1w = n1w + i*DMODEL;
        const float* L_n1b = n1b + i*DMODEL;
        const float* L_n2w = n2w + i*DMODEL;
        const float* L_n2b = n2b + i*DMODEL;
        const float* L_ipw = ipw + (size_t)i*2*DI*DMODEL;
        const float* L_cw  = cw  + (size_t)i*DI*DC;
        const float* L_cb  = cb  + (size_t)i*DI;
        const float* L_xpw = xpw + (size_t)i*(DTR+2*DS)*DI;
        const float* L_dpw = dpw + (size_t)i*DI*DTR;
        const float* L_dpb = dpb + (size_t)i*DI;
        const float* L_alog= alog+ (size_t)i*DI*DS;
        const float* L_skip= dskip+(size_t)i*DI;
        const float* L_opw = opw + (size_t)i*DMODEL*DI;
        const float* L_aiw = aiw + (size_t)i*3*DMODEL*DMODEL;
        const float* L_aib = aib + (size_t)i*3*DMODEL;
        const float* L_aow = aow + (size_t)i*DMODEL*DMODEL;
        const float* L_aob = aob + (size_t)i*DMODEL;

        // --- mamba branch ---
        k_ln<<<ROWS, 256>>>(ph, L_n1w, L_n1b, pxn, 0);
        // xz = xn @ ipw^T : [2048,1024]
        k_gemm<<<dim3((2*DI)/BN, ROWS/BM), 256>>>(pxn, DMODEL, L_ipw, DMODEL,
                                                  nullptr, pxz, 2*DI,
                                                  ROWS, 2*DI, DMODEL, 0, 0);
        k_conv<<<(ROWS*DI+255)/256, 256>>>(L_cw, L_cb);
        // xdbl = u @ xpw^T : [2048,48]
        k_gemm<<<dim3(1, ROWS/BM), 256>>>(pu, DI, L_xpw, DI,
                                          nullptr, pxdbl, DTR+2*DS,
                                          ROWS, DTR+2*DS, DI, 0, 0);
        // dt = softplus(xdbl[:, :16] @ dpw^T + dpb) : [2048,512]
        k_gemm<<<dim3(DI/BN, ROWS/BM), 256>>>(pxdbl, DTR+2*DS, L_dpw, DTR,
                                              L_dpb, pdt, DI,
                                              ROWS, DI, DTR, 1, 0);
        k_scan<<<dim3(DI/64, NREP), 1024>>>(L_alog, L_skip);
        k_gate<<<(ROWS*DI+255)/256, 256>>>();
        // h += gate @ opw^T : [2048,256]
        k_gemm<<<dim3(DMODEL/BN, ROWS/BM), 256>>>(pgate, DI, L_opw, DI,
                                                  nullptr, ph, DMODEL,
                                                  ROWS, DMODEL, DI, 0, 1);
        // --- attention branch ---
        k_ln<<<ROWS, 256>>>(ph, L_n2w, L_n2b, pxc, 1);
        // qkv = xc @ aiw^T + aib : [2048,768]
        k_gemm<<<dim3((3*DMODEL)/BN, ROWS/BM), 256>>>(pxc, DMODEL, L_aiw, DMODEL,
                                                      L_aib, pqkv, 3*DMODEL,
                                                      ROWS, 3*DMODEL, DMODEL, 0, 0);
        k_attn<<<LSEQ, 256>>>();
        // co = attno @ aow^T + aob : [2048,256]
        k_gemm<<<dim3(DMODEL/BN, ROWS/BM), 256>>>(pattno, DMODEL, L_aow, DMODEL,
                                                  L_aob, pco, DMODEL,
                                                  ROWS, DMODEL, DMODEL, 0, 0);
        k_scatter_add<<<(ROWS*DMODEL+255)/256, 256>>>();
    }

    k_mean<<<(LSEQ*DMODEL+255)/256, 256>>>();
    k_ln<<<LSEQ, 256>>>(phm, nfw, nfb, phf, 0);
    // logits = hf @ emb^T + head_b : [128, 32000]
    k_gemm<<<dim3(VOCAB/BN, (LSEQ+BM-1)/BM), 256>>>(phf, DMODEL, emb, DMODEL,
                                                    headb, out, VOCAB,
                                                    LSEQ, VOCAB, DMODEL, 0, 0);
}

// round 4
// speedup vs baseline: 1.2276x; 1.2276x over previous
#include <cuda_runtime.h>
#include <cuda_bf16.h>
#include <cstdint>
#include <math.h>

#define VOCAB 32000
#define DMODEL 256
#define NREP 16
#define NLAYER 6
#define DS 16
#define DC 4
#define DI 512
#define DTR 16
#define NH 4
#define HD 64
#define LSEQ 128
#define ROWS (NREP*LSEQ)   // 2048

// ---------------- scratch (device globals; no allocation allowed) ----------
__device__ float g_h[ROWS*DMODEL];        // residual stream [n*128+l, 256]
__device__ float g_xn[ROWS*DMODEL];       // ln1 out
__device__ float g_xz[ROWS*2*DI];         // in_proj out [2048,1024]
__device__ float g_u[ROWS*DI];            // conv+silu out
__device__ float g_xdbl[ROWS*(DTR+2*DS)]; // [2048,48]
__device__ float g_dt[ROWS*DI];           // softplus(dt)
__device__ float g_gate[ROWS*DI];         // y * silu(z)
__device__ float g_xc[ROWS*DMODEL];       // ln2 out, permuted rows l*16+n
__device__ float g_qkv[ROWS*3*DMODEL];    // [2048,768] rows l*16+n
__device__ float g_attno[ROWS*DMODEL];    // attention o (pre out-proj)
__device__ float g_hm[LSEQ*DMODEL];       // replica mean
__device__ float g_hf[LSEQ*DMODEL];       // final LN

// ---------------- helpers ----------
__device__ __forceinline__ float siluf(float x) {
    return x / (1.f + __expf(-x));
}

__device__ __forceinline__ uint32_t f2tf(float f) {
    uint32_t r;
    asm("cvt.rna.tf32.f32 %0, %1;" : "=r"(r) : "f"(f));
    return r;
}

__device__ __forceinline__ void mma8(float* c, const uint32_t* a, const uint32_t* b) {
    asm volatile(
        "mma.sync.aligned.m16n8k8.row.col.f32.tf32.tf32.f32 "
        "{%0,%1,%2,%3}, {%4,%5,%6,%7}, {%8,%9}, {%0,%1,%2,%3};"
        : "+f"(c[0]), "+f"(c[1]), "+f"(c[2]), "+f"(c[3])
        : "r"(a[0]), "r"(a[1]), "r"(a[2]), "r"(a[3]), "r"(b[0]), "r"(b[1]));
}

__device__ float blockReduceSum256(float v) {
    __shared__ float s[8];
    __shared__ float tot;
    int lane = threadIdx.x & 31, wid = threadIdx.x >> 5;
    #pragma unroll
    for (int o = 16; o > 0; o >>= 1) v += __shfl_xor_sync(0xffffffffu, v, o);
    if (lane == 0) s[wid] = v;
    __syncthreads();
    if (wid == 0) {
        float w = (lane < 8) ? s[lane] : 0.f;
        #pragma unroll
        for (int o = 4; o > 0; o >>= 1) w += __shfl_xor_sync(0xffffffffu, w, o);
        if (lane == 0) tot = w;
    }
    __syncthreads();
    float r = tot;
    __syncthreads();
    return r;
}

// ---------------- kernels ----------

__global__ void k_embed(const int* __restrict__ x, const float* __restrict__ emb) {
    int idx = blockIdx.x * blockDim.x + threadIdx.x;       // 16*128*256
    if (idx >= ROWS*DMODEL) return;
    int d = idx & (DMODEL-1);
    int r = idx >> 8;           // n*128+l
    int l = r & (LSEQ-1);
    g_h[idx] = emb[(size_t)x[l]*DMODEL + d];
}

// LayerNorm over 256. grid = nrows, block = 256.
__global__ void k_ln(const float* __restrict__ in, const float* __restrict__ w,
                     const float* __restrict__ b, float* __restrict__ out, int permuted) {
    int r = blockIdx.x;
    int d = threadIdx.x;
    float v = in[(size_t)r*DMODEL + d];
    float m = blockReduceSum256(v) * (1.f/DMODEL);
    float c = v - m;
    float var = blockReduceSum256(c*c) * (1.f/DMODEL);
    float res = c * rsqrtf(var + 1e-5f) * w[d] + b[d];
    if (permuted) {
        int n = r >> 7, l = r & (LSEQ-1);
        out[(size_t)((l<<4)+n)*DMODEL + d] = res;
    } else {
        out[(size_t)r*DMODEL + d] = res;
    }
}

// ---------------- tensor-core 3xTF32 GEMM (fp32-accurate) ----------------
// C[M,N] = act(A[M,K] @ W[N,K]^T + bias)
// mode: 0 = store, 1 = +=, 2 = permuted += (row l*16+n -> n*128+l)
#define TBM 128
#define TBN 64
#define TBK 32
#define TPAD 4
__global__ void k_gemm_tc(const float* __restrict__ A, int lda,
                          const float* __restrict__ W, int ldw,
                          const float* __restrict__ bias,
                          float* __restrict__ C, int ldc,
                          int M, int N, int K, int act, int mode) {
    __shared__ uint32_t Ash[TBM][TBK+TPAD];
    __shared__ uint32_t Asl[TBM][TBK+TPAD];
    __shared__ uint32_t Wsh[TBN][TBK+TPAD];
    __shared__ uint32_t Wsl[TBN][TBK+TPAD];
    int tid = threadIdx.x;
    int wid = tid >> 5, lane = tid & 31;
    int wm = wid >> 1, wn = wid & 1;    // 4 x 2 warp grid; warp tile 32x32
    int g = lane >> 2, t = lane & 3;
    int m0 = blockIdx.y * TBM, n0 = blockIdx.x * TBN;
    float acc[2][4][4] = {};

    for (int k0 = 0; k0 < K; k0 += TBK) {
        // A tile 128x32: each thread loads 4 float4s
        #pragma unroll
        for (int i = 0; i < 4; i++) {
            int m = (tid >> 3) + 32*i;
            int k = (tid & 7) * 4;
            int gm = m0 + m, gk = k0 + k;
            float4 v = make_float4(0.f,0.f,0.f,0.f);
            if (gm < M) {
                if (gk + 3 < K) {
                    v = *reinterpret_cast<const float4*>(&A[(size_t)gm*lda + gk]);
                } else {
                    if (gk+0 < K) v.x = A[(size_t)gm*lda+gk+0];
                    if (gk+1 < K) v.y = A[(size_t)gm*lda+gk+1];
                    if (gk+2 < K) v.z = A[(size_t)gm*lda+gk+2];
                    if (gk+3 < K) v.w = A[(size_t)gm*lda+gk+3];
                }
            }
            float e[4] = {v.x, v.y, v.z, v.w};
            #pragma unroll
            for (int j = 0; j < 4; j++) {
                uint32_t hi = f2tf(e[j]);
                Ash[m][k+j] = hi;
                Asl[m][k+j] = f2tf(e[j] - __uint_as_float(hi));
            }
        }
        // W tile 64x32: each thread loads 2 float4s
        #pragma unroll
        for (int i = 0; i < 2; i++) {
            int n = (tid >> 3) + 32*i;
            int k = (tid & 7) * 4;
            int gn = n0 + n, gk = k0 + k;
            float4 v = make_float4(0.f,0.f,0.f,0.f);
            if (gn < N) {
                if (gk + 3 < K) {
                    v = *reinterpret_cast<const float4*>(&W[(size_t)gn*ldw + gk]);
                } else {
                    if (gk+0 < K) v.x = W[(size_t)gn*ldw+gk+0];
                    if (gk+1 < K) v.y = W[(size_t)gn*ldw+gk+1];
                    if (gk+2 < K) v.z = W[(size_t)gn*ldw+gk+2];
                    if (gk+3 < K) v.w = W[(size_t)gn*ldw+gk+3];
                }
            }
            float e[4] = {v.x, v.y, v.z, v.w};
            #pragma unroll
            for (int j = 0; j < 4; j++) {
                uint32_t hi = f2tf(e[j]);
                Wsh[n][k+j] = hi;
                Wsl[n][k+j] = f2tf(e[j] - __uint_as_float(hi));
            }
        }
        __syncthreads();
        #pragma unroll
        for (int kk = 0; kk < TBK; kk += 8) {
            uint32_t ah[2][4], al[2][4], bh[4][2], bl[4][2];
            #pragma unroll
            for (int mf = 0; mf < 2; mf++) {
                int mr = wm*32 + mf*16;
                ah[mf][0] = Ash[mr + g    ][kk + t    ];
                ah[mf][1] = Ash[mr + 8 + g][kk + t    ];
                ah[mf][2] = Ash[mr + g    ][kk + t + 4];
                ah[mf][3] = Ash[mr + 8 + g][kk + t + 4];
                al[mf][0] = Asl[mr + g    ][kk + t    ];
                al[mf][1] = Asl[mr + 8 + g][kk + t    ];
                al[mf][2] = Asl[mr + g    ][kk + t + 4];
                al[mf][3] = Asl[mr + 8 + g][kk + t + 4];
            }
            #pragma unroll
            for (int nf = 0; nf < 4; nf++) {
                int nr = wn*32 + nf*8;
                bh[nf][0] = Wsh[nr + g][kk + t    ];
                bh[nf][1] = Wsh[nr + g][kk + t + 4];
                bl[nf][0] = Wsl[nr + g][kk + t    ];
                bl[nf][1] = Wsl[nr + g][kk + t + 4];
            }
            #pragma unroll
            for (int mf = 0; mf < 2; mf++)
                #pragma unroll
                for (int nf = 0; nf < 4; nf++) {
                    mma8(acc[mf][nf], al[mf], bh[nf]);   // lo*hi
                    mma8(acc[mf][nf], ah[mf], bl[nf]);   // hi*lo
                    mma8(acc[mf][nf], ah[mf], bh[nf]);   // hi*hi
                }
        }
        __syncthreads();
    }
    // epilogue
    #pragma unroll
    for (int mf = 0; mf < 2; mf++) {
        #pragma unroll
        for (int nf = 0; nf < 4; nf++) {
            #pragma unroll
            for (int e = 0; e < 4; e++) {
                int gm = m0 + wm*32 + mf*16 + g + (e >> 1) * 8;
                int gn = n0 + wn*32 + nf*8 + 2*t + (e & 1);
                if (gm < M && gn < N) {
                    float v = acc[mf][nf][e];
                    if (bias) v += bias[gn];
                    if (act == 1) v = (v > 20.f) ? v : log1pf(__expf(v));
                    if (mode == 0)      C[(size_t)gm*ldc + gn] = v;
                    else if (mode == 1) C[(size_t)gm*ldc + gn] += v;
                    else {
                        int l = gm >> 4, n = gm & 15;
                        C[(size_t)((n<<7)+l)*ldc + gn] += v;
                    }
                }
            }
        }
    }
}

// causal depthwise conv (DC=4) + bias + silu.  u in = xz[:, :512] (ld 1024)
__global__ void k_conv(const float* __restrict__ cw, const float* __restrict__ cb) {
    int idx = blockIdx.x * blockDim.x + threadIdx.x;   // 2048*512
    if (idx >= ROWS*DI) return;
    int c = idx & (DI-1);
    int r = idx >> 9;
    int t = r & (LSEQ-1);
    int b = r >> 7;
    float acc = cb[c];
    #pragma unroll
    for (int k = 0; k < DC; k++) {
        int tt = t - (DC-1) + k;
        if (tt >= 0) acc += g_xz[(size_t)((b<<7)+tt)*(2*DI) + c] * cw[c*DC + k];
    }
    g_u[idx] = siluf(acc);
}

// selective scan + fused gate. grid (DI/32, NREP), block 512: tid = s + 16*dl
__global__ void k_scan2(const float* __restrict__ A_log, const float* __restrict__ skipD) {
    __shared__ float sdt[LSEQ][32];  // recycled as y buffer
    __shared__ float su [LSEQ][32];
    __shared__ float sB [LSEQ][DS];
    __shared__ float sC [LSEQ][DS];
    int b = blockIdx.y, dchunk = blockIdx.x;
    int tid = threadIdx.x;
    for (int idx = tid; idx < LSEQ*32; idx += 512) {
        int tt = idx >> 5, dd = idx & 31;
        int row = (b<<7) + tt;
        sdt[tt][dd] = g_dt[(size_t)row*DI + dchunk*32 + dd];
        su [tt][dd] = g_u [(size_t)row*DI + dchunk*32 + dd];
    }
    for (int idx = tid; idx < LSEQ*DS; idx += 512) {
        int tt = idx >> 4, ss = idx & 15;
        int row = (b<<7) + tt;
        sB[tt][ss] = g_xdbl[(size_t)row*48 + DTR + ss];
        sC[tt][ss] = g_xdbl[(size_t)row*48 + DTR + DS + ss];
    }
    __syncthreads();
    int s = tid & 15, dl = tid >> 4;         // dl 0..31
    int d = dchunk*32 + dl;
    float Ads = -__expf(A_log[d*DS + s]);
    float skip = skipD[d];
    float h = 0.f;
    for (int t = 0; t < LSEQ; t++) {
        float dtv = sdt[t][dl], uv = su[t][dl];
        h = __expf(dtv*Ads)*h + dtv*uv*sB[t][s];
        float p = h * sC[t][s];
        p += __shfl_xor_sync(0xffffffffu, p, 8, 16);
        p += __shfl_xor_sync(0xffffffffu, p, 4, 16);
        p += __shfl_xor_sync(0xffffffffu, p, 2, 16);
        p += __shfl_xor_sync(0xffffffffu, p, 1, 16);
        if (s == 0) sdt[t][dl] = p + uv * skip;
    }
    __syncthreads();
    for (int idx = tid; idx < LSEQ*32; idx += 512) {
        int tt = idx >> 5, dd = idx & 31;
        int row = (b<<7) + tt;
        int gd = dchunk*32 + dd;
        float z = g_xz[(size_t)row*(2*DI) + DI + gd];
        g_gate[(size_t)row*DI + gd] = sdt[tt][dd] * siluf(z);
    }
}

// attention over the 16 replicas at each position l. grid=128, block=256.
__global__ void k_attn() {
    __shared__ float sK[NREP][DMODEL];
    __shared__ float sV[NREP][DMODEL];
    __shared__ float sS[NH][NREP][NREP];
    int l = blockIdx.x;
    int tid = threadIdx.x;
    for (int idx = tid; idx < NREP*DMODEL; idx += 256) {
        int n = idx >> 8, d = idx & (DMODEL-1);
        size_t base = (size_t)((l<<4)+n)*(3*DMODEL);
        sK[n][d] = g_qkv[base + DMODEL + d];
        sV[n][d] = g_qkv[base + 2*DMODEL + d];
    }
    __syncthreads();
    for (int idx = tid; idx < NH*NREP*NREP; idx += 256) {
        int h = idx >> 8;
        int i = (idx >> 4) & 15;
        int j = idx & 15;
        const float* q = &g_qkv[(size_t)((l<<4)+i)*(3*DMODEL) + h*HD];
        float dot = 0.f;
        #pragma unroll 8
        for (int dh = 0; dh < HD; dh++) dot += q[dh] * sK[j][h*HD + dh];
        sS[h][i][j] = dot * 0.125f;
    }
    __syncthreads();
    if (tid < NH*NREP) {
        int h = tid >> 4, i = tid & 15;
        float mx = -1e30f;
        #pragma unroll
        for (int j = 0; j < NREP; j++) mx = fmaxf(mx, sS[h][i][j]);
        float sum = 0.f;
        #pragma unroll
        for (int j = 0; j < NREP; j++) { float e = __expf(sS[h][i][j]-mx); sS[h][i][j] = e; sum += e; }
        float inv = 1.f/sum;
        #pragma unroll
        for (int j = 0; j < NREP; j++) sS[h][i][j] *= inv;
    }
    __syncthreads();
    for (int idx = tid; idx < NREP*DMODEL; idx += 256) {
        int i = idx >> 8, d = idx & (DMODEL-1);
        int h = d >> 6;
        float o = 0.f;
        #pragma unroll
        for (int j = 0; j < NREP; j++) o += sS[h][i][j] * sV[j][d];
        g_attno[(size_t)((l<<4)+i)*DMODEL + d] = o;
    }
}

// hm[l,d] = mean_n h[n,l,d]
__global__ void k_mean() {
    int idx = blockIdx.x * blockDim.x + threadIdx.x;   // 128*256
    if (idx >= LSEQ*DMODEL) return;
    int d = idx & (DMODEL-1);
    int l = idx >> 8;
    float s = 0.f;
    #pragma unroll
    for (int n = 0; n < NREP; n++) s += g_h[(size_t)((n<<7)+l)*DMODEL + d];
    g_hm[idx] = s * (1.f/NREP);
}

// ---------------- launch ----------
extern "C" void kernel_launch(void* const* d_in, const int* in_sizes, int n_in,
                              void* d_out, int out_size) {
    const int*   x     = (const int*)  d_in[0];
    const float* emb   = (const float*)d_in[1];
    const float* n1w   = (const float*)d_in[2];
    const float* n1b   = (const float*)d_in[3];
    const float* n2w   = (const float*)d_in[4];
    const float* n2b   = (const float*)d_in[5];
    const float* ipw   = (const float*)d_in[6];
    const float* cw    = (const float*)d_in[7];
    const float* cb    = (const float*)d_in[8];
    const float* xpw   = (const float*)d_in[9];
    const float* dpw   = (const float*)d_in[10];
    const float* dpb   = (const float*)d_in[11];
    const float* alog  = (const float*)d_in[12];
    const float* dskip = (const float*)d_in[13];
    const float* opw   = (const float*)d_in[14];
    const float* aiw   = (const float*)d_in[15];
    const float* aib   = (const float*)d_in[16];
    const float* aow   = (const float*)d_in[17];
    const float* aob   = (const float*)d_in[18];
    const float* nfw   = (const float*)d_in[19];
    const float* nfb   = (const float*)d_in[20];
    const float* headb = (const float*)d_in[21];
    float* out = (float*)d_out;

    float* ph;    cudaGetSymbolAddress((void**)&ph, g_h);
    float* pxn;   cudaGetSymbolAddress((void**)&pxn, g_xn);
    float* pxz;   cudaGetSymbolAddress((void**)&pxz, g_xz);
    float* pu;    cudaGetSymbolAddress((void**)&pu, g_u);
    float* pxdbl; cudaGetSymbolAddress((void**)&pxdbl, g_xdbl);
    float* pdt;   cudaGetSymbolAddress((void**)&pdt, g_dt);
    float* pgate; cudaGetSymbolAddress((void**)&pgate, g_gate);
    float* pxc;   cudaGetSymbolAddress((void**)&pxc, g_xc);
    float* pqkv;  cudaGetSymbolAddress((void**)&pqkv, g_qkv);
    float* pattno;cudaGetSymbolAddress((void**)&pattno, g_attno);
    float* phm;   cudaGetSymbolAddress((void**)&phm, g_hm);
    float* phf;   cudaGetSymbolAddress((void**)&phf, g_hf);

    k_embed<<<(ROWS*DMODEL+255)/256, 256>>>(x, emb);

    for (int i = 0; i < NLAYER; i++) {
        const float* L_n1w = n1w + i*DMODEL;
        const float* L_n1b = n1b + i*DMODEL;
        const float* L_n2w = n2w + i*DMODEL;
        const float* L_n2b = n2b + i*DMODEL;
        const float* L_ipw = ipw + (size_t)i*2*DI*DMODEL;
        const float* L_cw  = cw  + (size_t)i*DI*DC;
        const float* L_cb  = cb  + (size_t)i*DI;
        const float* L_xpw = xpw + (size_t)i*(DTR+2*DS)*DI;
        const float* L_dpw = dpw + (size_t)i*DI*DTR;
        const float* L_dpb = dpb + (size_t)i*DI;
        const float* L_alog= alog+ (size_t)i*DI*DS;
        const float* L_skip= dskip+(size_t)i*DI;
        const float* L_opw = opw + (size_t)i*DMODEL*DI;
        const float* L_aiw = aiw + (size_t)i*3*DMODEL*DMODEL;
        const float* L_aib = aib + (size_t)i*3*DMODEL;
        const float* L_aow = aow + (size_t)i*DMODEL*DMODEL;
        const float* L_aob = aob + (size_t)i*DMODEL;

        // --- mamba branch ---
        k_ln<<<ROWS, 256>>>(ph, L_n1w, L_n1b, pxn, 0);
        k_gemm_tc<<<dim3((2*DI)/TBN, ROWS/TBM), 256>>>(pxn, DMODEL, L_ipw, DMODEL,
                                                       nullptr, pxz, 2*DI,
                                                       ROWS, 2*DI, DMODEL, 0, 0);
        k_conv<<<(ROWS*DI+255)/256, 256>>>(L_cw, L_cb);
        k_gemm_tc<<<dim3(1, ROWS/TBM), 256>>>(pu, DI, L_xpw, DI,
                                              nullptr, pxdbl, DTR+2*DS,
                                              ROWS, DTR+2*DS, DI, 0, 0);
        k_gemm_tc<<<dim3(DI/TBN, ROWS/TBM), 256>>>(pxdbl, DTR+2*DS, L_dpw, DTR,
                                                   L_dpb, pdt, DI,
                                                   ROWS, DI, DTR, 1, 0);
        k_scan2<<<dim3(DI/32, NREP), 512>>>(L_alog, L_skip);
        k_gemm_tc<<<dim3(DMODEL/TBN, ROWS/TBM), 256>>>(pgate, DI, L_opw, DI,
                                                       nullptr, ph, DMODEL,
                                                       ROWS, DMODEL, DI, 0, 1);
        // --- attention branch ---
        k_ln<<<ROWS, 256>>>(ph, L_n2w, L_n2b, pxc, 1);
        k_gemm_tc<<<dim3((3*DMODEL)/TBN, ROWS/TBM), 256>>>(pxc, DMODEL, L_aiw, DMODEL,
                                                           L_aib, pqkv, 3*DMODEL,
                                                           ROWS, 3*DMODEL, DMODEL, 0, 0);
        k_attn<<<LSEQ, 256>>>();
        k_gemm_tc<<<dim3(DMODEL/TBN, ROWS/TBM), 256>>>(pattno, DMODEL, L_aow, DMODEL,
                                                       L_aob, ph, DMODEL,
                                                       ROWS, DMODEL, DMODEL, 0, 2);
    }

    k_mean<<<(LSEQ*DMODEL+255)/256, 256>>>();
    k_ln<<<LSEQ, 256>>>(phm, nfw, nfb, phf, 0);
    k_gemm_tc<<<dim3((VOCAB+TBN-1)/TBN, 1), 256>>>(phf, DMODEL, emb, DMODEL,
                                                   headb, out, VOCAB,
                                                   LSEQ, VOCAB, DMODEL, 0, 0);
}

// round 5
// speedup vs baseline: 1.9116x; 1.5572x over previous
#include <cuda_runtime.h>
#include <cuda_bf16.h>
#include <cstdint>
#include <math.h>

#define VOCAB 32000
#define DMODEL 256
#define NREP 16
#define NLAYER 6
#define DS 16
#define DC 4
#define DI 512
#define DTR 16
#define NH 4
#define HD 64
#define LSEQ 128
#define ROWS (NREP*LSEQ)   // 2048

// ---------------- scratch (device globals; no allocation allowed) ----------
__device__ float g_h[ROWS*DMODEL];        // residual stream [n*128+l, 256]
__device__ float g_xn[ROWS*DMODEL];       // ln1 out
__device__ float g_xz[ROWS*2*DI];         // in_proj out [2048,1024]
__device__ float g_u[ROWS*DI];            // conv+silu out
__device__ float g_xdbl[ROWS*(DTR+2*DS)]; // [2048,48]
__device__ float g_dt[ROWS*DI];           // softplus(dt)
__device__ float g_gate[ROWS*DI];         // y * silu(z)
__device__ float g_xc[ROWS*DMODEL];       // ln2 out, permuted rows l*16+n
__device__ float g_qkv[ROWS*3*DMODEL];    // [2048,768] rows l*16+n
__device__ float g_attno[ROWS*DMODEL];    // attention o (pre out-proj)
__device__ float g_hm[LSEQ*DMODEL];       // replica mean
__device__ float g_hf[LSEQ*DMODEL];       // final LN

// ---------------- helpers ----------
__device__ __forceinline__ float siluf(float x) {
    return x / (1.f + __expf(-x));
}

__device__ __forceinline__ uint32_t packbf(float x, float y) {
    __nv_bfloat162 h = __floats2bfloat162_rn(x, y);
    return *reinterpret_cast<uint32_t*>(&h);
}

// bf16 m16n8k16 mma, fp32 accumulate
__device__ __forceinline__ void mma16(float* c, const uint32_t* a, const uint32_t* b) {
    asm volatile(
        "mma.sync.aligned.m16n8k16.row.col.f32.bf16.bf16.f32 "
        "{%0,%1,%2,%3}, {%4,%5,%6,%7}, {%8,%9}, {%0,%1,%2,%3};"
        : "+f"(c[0]), "+f"(c[1]), "+f"(c[2]), "+f"(c[3])
        : "r"(a[0]), "r"(a[1]), "r"(a[2]), "r"(a[3]), "r"(b[0]), "r"(b[1]));
}

__device__ float blockReduceSum256(float v) {
    __shared__ float s[8];
    __shared__ float tot;
    int lane = threadIdx.x & 31, wid = threadIdx.x >> 5;
    #pragma unroll
    for (int o = 16; o > 0; o >>= 1) v += __shfl_xor_sync(0xffffffffu, v, o);
    if (lane == 0) s[wid] = v;
    __syncthreads();
    if (wid == 0) {
        float w = (lane < 8) ? s[lane] : 0.f;
        #pragma unroll
        for (int o = 4; o > 0; o >>= 1) w += __shfl_xor_sync(0xffffffffu, w, o);
        if (lane == 0) tot = w;
    }
    __syncthreads();
    float r = tot;
    __syncthreads();
    return r;
}

// ---------------- kernels ----------

__global__ void k_embed(const int* __restrict__ x, const float* __restrict__ emb) {
    int idx = blockIdx.x * blockDim.x + threadIdx.x;       // 16*128*256
    if (idx >= ROWS*DMODEL) return;
    int d = idx & (DMODEL-1);
    int r = idx >> 8;           // n*128+l
    int l = r & (LSEQ-1);
    g_h[idx] = emb[(size_t)x[l]*DMODEL + d];
}

// LayerNorm over 256. grid = nrows, block = 256.
__global__ void k_ln(const float* __restrict__ in, const float* __restrict__ w,
                     const float* __restrict__ b, float* __restrict__ out, int permuted) {
    int r = blockIdx.x;
    int d = threadIdx.x;
    float v = in[(size_t)r*DMODEL + d];
    float m = blockReduceSum256(v) * (1.f/DMODEL);
    float c = v - m;
    float var = blockReduceSum256(c*c) * (1.f/DMODEL);
    float res = c * rsqrtf(var + 1e-5f) * w[d] + b[d];
    if (permuted) {
        int n = r >> 7, l = r & (LSEQ-1);
        out[(size_t)((l<<4)+n)*DMODEL + d] = res;
    } else {
        out[(size_t)r*DMODEL + d] = res;
    }
}

// ---------------- tensor-core split-bf16 GEMM (near-fp32 accurate) --------
// C[M,N] = act(A[M,K] @ W[N,K]^T + bias)
// mode: 0 = store, 1 = +=, 2 = permuted += (row l*16+n -> n*128+l)
// Each fp32 x = hi(bf16) + lo(bf16); D = Ah*Bh + Ah*Bl + Al*Bh (fp32 accum).
#define TBM 128
#define TBN 64
#define TBK 16
#define SW 12           // padded words per row (8 data + 4 pad): conflict-free frag loads
__global__ void k_gemm_tc(const float* __restrict__ A, int lda,
                          const float* __restrict__ W, int ldw,
                          const float* __restrict__ bias,
                          float* __restrict__ C, int ldc,
                          int M, int N, int K, int act, int mode) {
    __shared__ uint32_t Ash[2][TBM][SW];
    __shared__ uint32_t Asl[2][TBM][SW];
    __shared__ uint32_t Wsh[2][TBN][SW];
    __shared__ uint32_t Wsl[2][TBN][SW];
    int tid = threadIdx.x;
    int wid = tid >> 5, lane = tid & 31;
    int wm = wid >> 1, wn = wid & 1;    // 4 x 2 warp grid; warp tile 32x32
    int g = lane >> 2, t = lane & 3;
    int m0 = blockIdx.y * TBM, n0 = blockIdx.x * TBN;
    float acc[2][4][4] = {};

    int am = (tid >> 2);            // 0..63
    int ak = (tid & 3) * 4;         // 0,4,8,12
    float4 rA[2], rW;

    // ---- tile loader (global -> regs) ----
    auto load_tile = [&](int k0) {
        #pragma unroll
        for (int i = 0; i < 2; i++) {
            int gm = m0 + am + 64*i, gk = k0 + ak;
            float4 v = make_float4(0.f,0.f,0.f,0.f);
            if (gm < M && gk < K) {
                if (gk + 3 < K) v = *reinterpret_cast<const float4*>(&A[(size_t)gm*lda + gk]);
                else {
                    v.x = A[(size_t)gm*lda+gk];
                    if (gk+1 < K) v.y = A[(size_t)gm*lda+gk+1];
                    if (gk+2 < K) v.z = A[(size_t)gm*lda+gk+2];
                }
            }
            rA[i] = v;
        }
        {
            int gn = n0 + am, gk = k0 + ak;
            float4 v = make_float4(0.f,0.f,0.f,0.f);
            if (gn < N && gk < K) {
                if (gk + 3 < K) v = *reinterpret_cast<const float4*>(&W[(size_t)gn*ldw + gk]);
                else {
                    v.x = W[(size_t)gn*ldw+gk];
                    if (gk+1 < K) v.y = W[(size_t)gn*ldw+gk+1];
                    if (gk+2 < K) v.z = W[(size_t)gn*ldw+gk+2];
                }
            }
            rW = v;
        }
    };
    // ---- split + store regs -> smem stage s ----
    auto store_tile = [&](int s) {
        int kw = ak >> 1;   // word index (0,2,4,6)
        #pragma unroll
        for (int i = 0; i < 2; i++) {
            float4 v = rA[i];
            uint32_t h0 = packbf(v.x, v.y), h1 = packbf(v.z, v.w);
            __nv_bfloat162 b0 = *reinterpret_cast<__nv_bfloat162*>(&h0);
            __nv_bfloat162 b1 = *reinterpret_cast<__nv_bfloat162*>(&h1);
            uint32_t l0 = packbf(v.x - __low2float(b0), v.y - __high2float(b0));
            uint32_t l1 = packbf(v.z - __low2float(b1), v.w - __high2float(b1));
            int m = am + 64*i;
            Ash[s][m][kw]   = h0; Ash[s][m][kw+1] = h1;
            Asl[s][m][kw]   = l0; Asl[s][m][kw+1] = l1;
        }
        {
            float4 v = rW;
            uint32_t h0 = packbf(v.x, v.y), h1 = packbf(v.z, v.w);
            __nv_bfloat162 b0 = *reinterpret_cast<__nv_bfloat162*>(&h0);
            __nv_bfloat162 b1 = *reinterpret_cast<__nv_bfloat162*>(&h1);
            uint32_t l0 = packbf(v.x - __low2float(b0), v.y - __high2float(b0));
            uint32_t l1 = packbf(v.z - __low2float(b1), v.w - __high2float(b1));
            Wsh[s][am][kw]   = h0; Wsh[s][am][kw+1] = h1;
            Wsl[s][am][kw]   = l0; Wsl[s][am][kw+1] = l1;
        }
    };

    int nt = (K + TBK - 1) / TBK;
    load_tile(0);
    store_tile(0);
    __syncthreads();

    for (int it = 0; it < nt; it++) {
        int cur = it & 1;
        if (it + 1 < nt) load_tile((it+1) * TBK);
        // fragments + MMA from stage cur
        uint32_t ah[2][4], al[2][4], bh[4][2], bl[4][2];
        #pragma unroll
        for (int mf = 0; mf < 2; mf++) {
            int mr = wm*32 + mf*16;
            ah[mf][0] = Ash[cur][mr + g    ][t    ];
            ah[mf][1] = Ash[cur][mr + 8 + g][t    ];
            ah[mf][2] = Ash[cur][mr + g    ][t + 4];
            ah[mf][3] = Ash[cur][mr + 8 + g][t + 4];
            al[mf][0] = Asl[cur][mr + g    ][t    ];
            al[mf][1] = Asl[cur][mr + 8 + g][t    ];
            al[mf][2] = Asl[cur][mr + g    ][t + 4];
            al[mf][3] = Asl[cur][mr + 8 + g][t + 4];
        }
        #pragma unroll
        for (int nf = 0; nf < 4; nf++) {
            int nr = wn*32 + nf*8;
            bh[nf][0] = Wsh[cur][nr + g][t    ];
            bh[nf][1] = Wsh[cur][nr + g][t + 4];
            bl[nf][0] = Wsl[cur][nr + g][t    ];
            bl[nf][1] = Wsl[cur][nr + g][t + 4];
        }
        #pragma unroll
        for (int mf = 0; mf < 2; mf++)
            #pragma unroll
            for (int nf = 0; nf < 4; nf++) {
                mma16(acc[mf][nf], al[mf], bh[nf]);   // lo*hi
                mma16(acc[mf][nf], ah[mf], bl[nf]);   // hi*lo
                mma16(acc[mf][nf], ah[mf], bh[nf]);   // hi*hi
            }
        if (it + 1 < nt) store_tile(cur ^ 1);
        __syncthreads();
    }

    // epilogue
    #pragma unroll
    for (int mf = 0; mf < 2; mf++) {
        #pragma unroll
        for (int nf = 0; nf < 4; nf++) {
            #pragma unroll
            for (int e = 0; e < 4; e++) {
                int gm = m0 + wm*32 + mf*16 + g + (e >> 1) * 8;
                int gn = n0 + wn*32 + nf*8 + 2*t + (e & 1);
                if (gm < M && gn < N) {
                    float v = acc[mf][nf][e];
                    if (bias) v += bias[gn];
                    if (act == 1) v = (v > 20.f) ? v : log1pf(__expf(v));
                    if (mode == 0)      C[(size_t)gm*ldc + gn] = v;
                    else if (mode == 1) C[(size_t)gm*ldc + gn] += v;
                    else {
                        int l = gm >> 4, n = gm & 15;
                        C[(size_t)((n<<7)+l)*ldc + gn] += v;
                    }
                }
            }
        }
    }
}

// causal depthwise conv (DC=4) + bias + silu.  u in = xz[:, :512] (ld 1024)
__global__ void k_conv(const float* __restrict__ cw, const float* __restrict__ cb) {
    int idx = blockIdx.x * blockDim.x + threadIdx.x;   // 2048*512
    if (idx >= ROWS*DI) return;
    int c = idx & (DI-1);
    int r = idx >> 9;
    int t = r & (LSEQ-1);
    int b = r >> 7;
    float acc = cb[c];
    #pragma unroll
    for (int k = 0; k < DC; k++) {
        int tt = t - (DC-1) + k;
        if (tt >= 0) acc += g_xz[(size_t)((b<<7)+tt)*(2*DI) + c] * cw[c*DC + k];
    }
    g_u[idx] = siluf(acc);
}

// selective scan + fused gate. grid (DI/32, NREP), block 512: tid = s + 16*dl
__global__ void k_scan2(const float* __restrict__ A_log, const float* __restrict__ skipD) {
    __shared__ float sdt[LSEQ][32];  // recycled as y buffer
    __shared__ float su [LSEQ][32];
    __shared__ float sB [LSEQ][DS];
    __shared__ float sC [LSEQ][DS];
    int b = blockIdx.y, dchunk = blockIdx.x;
    int tid = threadIdx.x;
    for (int idx = tid; idx < LSEQ*32; idx += 512) {
        int tt = idx >> 5, dd = idx & 31;
        int row = (b<<7) + tt;
        sdt[tt][dd] = g_dt[(size_t)row*DI + dchunk*32 + dd];
        su [tt][dd] = g_u [(size_t)row*DI + dchunk*32 + dd];
    }
    for (int idx = tid; idx < LSEQ*DS; idx += 512) {
        int tt = idx >> 4, ss = idx & 15;
        int row = (b<<7) + tt;
        sB[tt][ss] = g_xdbl[(size_t)row*48 + DTR + ss];
        sC[tt][ss] = g_xdbl[(size_t)row*48 + DTR + DS + ss];
    }
    __syncthreads();
    int s = tid & 15, dl = tid >> 4;         // dl 0..31
    int d = dchunk*32 + dl;
    float Ads = -__expf(A_log[d*DS + s]);
    float skip = skipD[d];
    float h = 0.f;
    for (int t = 0; t < LSEQ; t++) {
        float dtv = sdt[t][dl], uv = su[t][dl];
        h = __expf(dtv*Ads)*h + dtv*uv*sB[t][s];
        float p = h * sC[t][s];
        p += __shfl_xor_sync(0xffffffffu, p, 8, 16);
        p += __shfl_xor_sync(0xffffffffu, p, 4, 16);
        p += __shfl_xor_sync(0xffffffffu, p, 2, 16);
        p += __shfl_xor_sync(0xffffffffu, p, 1, 16);
        if (s == 0) sdt[t][dl] = p + uv * skip;
    }
    __syncthreads();
    for (int idx = tid; idx < LSEQ*32; idx += 512) {
        int tt = idx >> 5, dd = idx & 31;
        int row = (b<<7) + tt;
        int gd = dchunk*32 + dd;
        float z = g_xz[(size_t)row*(2*DI) + DI + gd];
        g_gate[(size_t)row*DI + gd] = sdt[tt][dd] * siluf(z);
    }
}

// attention over the 16 replicas at each position l. grid=128, block=256.
__global__ void k_attn() {
    __shared__ float sK[NREP][DMODEL];
    __shared__ float sV[NREP][DMODEL];
    __shared__ float sS[NH][NREP][NREP];
    int l = blockIdx.x;
    int tid = threadIdx.x;
    for (int idx = tid; idx < NREP*DMODEL; idx += 256) {
        int n = idx >> 8, d = idx & (DMODEL-1);
        size_t base = (size_t)((l<<4)+n)*(3*DMODEL);
        sK[n][d] = g_qkv[base + DMODEL + d];
        sV[n][d] = g_qkv[base + 2*DMODEL + d];
    }
    __syncthreads();
    for (int idx = tid; idx < NH*NREP*NREP; idx += 256) {
        int h = idx >> 8;
        int i = (idx >> 4) & 15;
        int j = idx & 15;
        const float* q = &g_qkv[(size_t)((l<<4)+i)*(3*DMODEL) + h*HD];
        float dot = 0.f;
        #pragma unroll 8
        for (int dh = 0; dh < HD; dh++) dot += q[dh] * sK[j][h*HD + dh];
        sS[h][i][j] = dot * 0.125f;
    }
    __syncthreads();
    if (tid < NH*NREP) {
        int h = tid >> 4, i = tid & 15;
        float mx = -1e30f;
        #pragma unroll
        for (int j = 0; j < NREP; j++) mx = fmaxf(mx, sS[h][i][j]);
        float sum = 0.f;
        #pragma unroll
        for (int j = 0; j < NREP; j++) { float e = __expf(sS[h][i][j]-mx); sS[h][i][j] = e; sum += e; }
        float inv = 1.f/sum;
        #pragma unroll
        for (int j = 0; j < NREP; j++) sS[h][i][j] *= inv;
    }
    __syncthreads();
    for (int idx = tid; idx < NREP*DMODEL; idx += 256) {
        int i = idx >> 8, d = idx & (DMODEL-1);
        int h = d >> 6;
        float o = 0.f;
        #pragma unroll
        for (int j = 0; j < NREP; j++) o += sS[h][i][j] * sV[j][d];
        g_attno[(size_t)((l<<4)+i)*DMODEL + d] = o;
    }
}

// hm[l,d] = mean_n h[n,l,d]
__global__ void k_mean() {
    int idx = blockIdx.x * blockDim.x + threadIdx.x;   // 128*256
    if (idx >= LSEQ*DMODEL) return;
    int d = idx & (DMODEL-1);
    int l = idx >> 8;
    float s = 0.f;
    #pragma unroll
    for (int n = 0; n < NREP; n++) s += g_h[(size_t)((n<<7)+l)*DMODEL + d];
    g_hm[idx] = s * (1.f/NREP);
}

// ---------------- launch ----------
extern "C" void kernel_launch(void* const* d_in, const int* in_sizes, int n_in,
                              void* d_out, int out_size) {
    const int*   x     = (const int*)  d_in[0];
    const float* emb   = (const float*)d_in[1];
    const float* n1w   = (const float*)d_in[2];
    const float* n1b   = (const float*)d_in[3];
    const float* n2w   = (const float*)d_in[4];
    const float* n2b   = (const float*)d_in[5];
    const float* ipw   = (const float*)d_in[6];
    const float* cw    = (const float*)d_in[7];
    const float* cb    = (const float*)d_in[8];
    const float* xpw   = (const float*)d_in[9];
    const float* dpw   = (const float*)d_in[10];
    const float* dpb   = (const float*)d_in[11];
    const float* alog  = (const float*)d_in[12];
    const float* dskip = (const float*)d_in[13];
    const float* opw   = (const float*)d_in[14];
    const float* aiw   = (const float*)d_in[15];
    const float* aib   = (const float*)d_in[16];
    const float* aow   = (const float*)d_in[17];
    const float* aob   = (const float*)d_in[18];
    const float* nfw   = (const float*)d_in[19];
    const float* nfb   = (const float*)d_in[20];
    const float* headb = (const float*)d_in[21];
    float* out = (float*)d_out;

    float* ph;    cudaGetSymbolAddress((void**)&ph, g_h);
    float* pxn;   cudaGetSymbolAddress((void**)&pxn, g_xn);
    float* pxz;   cudaGetSymbolAddress((void**)&pxz, g_xz);
    float* pu;    cudaGetSymbolAddress((void**)&pu, g_u);
    float* pxdbl; cudaGetSymbolAddress((void**)&pxdbl, g_xdbl);
    float* pdt;   cudaGetSymbolAddress((void**)&pdt, g_dt);
    float* pgate; cudaGetSymbolAddress((void**)&pgate, g_gate);
    float* pxc;   cudaGetSymbolAddress((void**)&pxc, g_xc);
    float* pqkv;  cudaGetSymbolAddress((void**)&pqkv, g_qkv);
    float* pattno;cudaGetSymbolAddress((void**)&pattno, g_attno);
    float* phm;   cudaGetSymbolAddress((void**)&phm, g_hm);
    float* phf;   cudaGetSymbolAddress((void**)&phf, g_hf);

    k_embed<<<(ROWS*DMODEL+255)/256, 256>>>(x, emb);

    for (int i = 0; i < NLAYER; i++) {
        const float* L_n1w = n1w + i*DMODEL;
        const float* L_n1b = n1b + i*DMODEL;
        const float* L_n2w = n2w + i*DMODEL;
        const float* L_n2b = n2b + i*DMODEL;
        const float* L_ipw = ipw + (size_t)i*2*DI*DMODEL;
        const float* L_cw  = cw  + (size_t)i*DI*DC;
        const float* L_cb  = cb  + (size_t)i*DI;
        const float* L_xpw = xpw + (size_t)i*(DTR+2*DS)*DI;
        const float* L_dpw = dpw + (size_t)i*DI*DTR;
        const float* L_dpb = dpb + (size_t)i*DI;
        const float* L_alog= alog+ (size_t)i*DI*DS;
        const float* L_skip= dskip+(size_t)i*DI;
        const float* L_opw = opw + (size_t)i*DMODEL*DI;
        const float* L_aiw = aiw + (size_t)i*3*DMODEL*DMODEL;
        const float* L_aib = aib + (size_t)i*3*DMODEL;
        const float* L_aow = aow + (size_t)i*DMODEL*DMODEL;
        const float* L_aob = aob + (size_t)i*DMODEL;

        // --- mamba branch ---
        k_ln<<<ROWS, 256>>>(ph, L_n1w, L_n1b, pxn, 0);
        k_gemm_tc<<<dim3((2*DI)/TBN, ROWS/TBM), 256>>>(pxn, DMODEL, L_ipw, DMODEL,
                                                       nullptr, pxz, 2*DI,
                                                       ROWS, 2*DI, DMODEL, 0, 0);
        k_conv<<<(ROWS*DI+255)/256, 256>>>(L_cw, L_cb);
        k_gemm_tc<<<dim3(1, ROWS/TBM), 256>>>(pu, DI, L_xpw, DI,
                                              nullptr, pxdbl, DTR+2*DS,
                                              ROWS, DTR+2*DS, DI, 0, 0);
        k_gemm_tc<<<dim3(DI/TBN, ROWS/TBM), 256>>>(pxdbl, DTR+2*DS, L_dpw, DTR,
                                                   L_dpb, pdt, DI,
                                                   ROWS, DI, DTR, 1, 0);
        k_scan2<<<dim3(DI/32, NREP), 512>>>(L_alog, L_skip);
        k_gemm_tc<<<dim3(DMODEL/TBN, ROWS/TBM), 256>>>(pgate, DI, L_opw, DI,
                                                       nullptr, ph, DMODEL,
                                                       ROWS, DMODEL, DI, 0, 1);
        // --- attention branch ---
        k_ln<<<ROWS, 256>>>(ph, L_n2w, L_n2b, pxc, 1);
        k_gemm_tc<<<dim3((3*DMODEL)/TBN, ROWS/TBM), 256>>>(pxc, DMODEL, L_aiw, DMODEL,
                                                           L_aib, pqkv, 3*DMODEL,
                                                           ROWS, 3*DMODEL, DMODEL, 0, 0);
        k_attn<<<LSEQ, 256>>>();
        k_gemm_tc<<<dim3(DMODEL/TBN, ROWS/TBM), 256>>>(pattno, DMODEL, L_aow, DMODEL,
                                                       L_aob, ph, DMODEL,
                                                       ROWS, DMODEL, DMODEL, 0, 2);
    }

    k_mean<<<(LSEQ*DMODEL+255)/256, 256>>>();
    k_ln<<<LSEQ, 256>>>(phm, nfw, nfb, phf, 0);
    k_gemm_tc<<<dim3((VOCAB+TBN-1)/TBN, 1), 256>>>(phf, DMODEL, emb, DMODEL,
                                                   headb, out, VOCAB,
                                                   LSEQ, VOCAB, DMODEL, 0, 0);
}

// round 6
// speedup vs baseline: 2.9782x; 1.5579x over previous
#include <cuda_runtime.h>
#include <cuda_bf16.h>
#include <cstdint>
#include <math.h>

#define VOCAB 32000
#define DMODEL 256
#define NREP 16
#define NLAYER 6
#define DS 16
#define DC 4
#define DI 512
#define DTR 16
#define NH 4
#define HD 64
#define LSEQ 128
#define ROWS (NREP*LSEQ)   // 2048

// ---------------- scratch (device globals; no allocation allowed) ----------
__device__ float g_h[ROWS*DMODEL];        // residual stream [n*128+l, 256]
__device__ float g_xn[ROWS*DMODEL];       // ln1 out
__device__ float g_z[ROWS*DI];            // z half of in_proj
__device__ float g_u[ROWS*DI];            // conv+silu out
__device__ float g_xdbl[ROWS*(DTR+2*DS)]; // [2048,48]
__device__ float g_dt[ROWS*DI];           // softplus(dt)
__device__ float g_gate[ROWS*DI];         // y * silu(z)
__device__ float g_xc[ROWS*DMODEL];       // ln2 out, permuted rows l*16+n
__device__ float g_qkv[ROWS*3*DMODEL];    // [2048,768] rows l*16+n
__device__ float g_attno[ROWS*DMODEL];    // attention o (pre out-proj)
__device__ float g_hf[LSEQ*DMODEL];       // mean + final LN

// ---------------- helpers ----------
__device__ __forceinline__ float siluf(float x) {
    return x / (1.f + __expf(-x));
}

__device__ __forceinline__ uint32_t packbf(float x, float y) {
    __nv_bfloat162 h = __floats2bfloat162_rn(x, y);
    return *reinterpret_cast<uint32_t*>(&h);
}

// bf16 m16n8k16 mma, fp32 accumulate
__device__ __forceinline__ void mma16(float* c, const uint32_t* a, const uint32_t* b) {
    asm volatile(
        "mma.sync.aligned.m16n8k16.row.col.f32.bf16.bf16.f32 "
        "{%0,%1,%2,%3}, {%4,%5,%6,%7}, {%8,%9}, {%0,%1,%2,%3};"
        : "+f"(c[0]), "+f"(c[1]), "+f"(c[2]), "+f"(c[3])
        : "r"(a[0]), "r"(a[1]), "r"(a[2]), "r"(a[3]), "r"(b[0]), "r"(b[1]));
}

__device__ float blockReduceSum256(float v) {
    __shared__ float s[8];
    __shared__ float tot;
    int lane = threadIdx.x & 31, wid = threadIdx.x >> 5;
    #pragma unroll
    for (int o = 16; o > 0; o >>= 1) v += __shfl_xor_sync(0xffffffffu, v, o);
    if (lane == 0) s[wid] = v;
    __syncthreads();
    if (wid == 0) {
        float w = (lane < 8) ? s[lane] : 0.f;
        #pragma unroll
        for (int o = 4; o > 0; o >>= 1) w += __shfl_xor_sync(0xffffffffu, w, o);
        if (lane == 0) tot = w;
    }
    __syncthreads();
    float r = tot;
    __syncthreads();
    return r;
}

// ---------------- kernels ----------

__global__ void k_embed(const int* __restrict__ x, const float* __restrict__ emb) {
    int idx = blockIdx.x * blockDim.x + threadIdx.x;       // 16*128*256
    if (idx >= ROWS*DMODEL) return;
    int d = idx & (DMODEL-1);
    int r = idx >> 8;           // n*128+l
    int l = r & (LSEQ-1);
    g_h[idx] = emb[(size_t)x[l]*DMODEL + d];
}

// LayerNorm over 256. grid = nrows, block = 256.
__global__ void k_ln(const float* __restrict__ in, const float* __restrict__ w,
                     const float* __restrict__ b, float* __restrict__ out, int permuted) {
    int r = blockIdx.x;
    int d = threadIdx.x;
    float v = in[(size_t)r*DMODEL + d];
    float m = blockReduceSum256(v) * (1.f/DMODEL);
    float c = v - m;
    float var = blockReduceSum256(c*c) * (1.f/DMODEL);
    float res = c * rsqrtf(var + 1e-5f) * w[d] + b[d];
    if (permuted) {
        int n = r >> 7, l = r & (LSEQ-1);
        out[(size_t)((l<<4)+n)*DMODEL + d] = res;
    } else {
        out[(size_t)r*DMODEL + d] = res;
    }
}

// replica mean + final LayerNorm. grid = LSEQ, block = 256.
__global__ void k_meanln(const float* __restrict__ w, const float* __restrict__ b) {
    int l = blockIdx.x;
    int d = threadIdx.x;
    float v = 0.f;
    #pragma unroll
    for (int n = 0; n < NREP; n++) v += g_h[(size_t)((n<<7)+l)*DMODEL + d];
    v *= (1.f/NREP);
    float m = blockReduceSum256(v) * (1.f/DMODEL);
    float c = v - m;
    float var = blockReduceSum256(c*c) * (1.f/DMODEL);
    g_hf[(size_t)l*DMODEL + d] = c * rsqrtf(var + 1e-5f) * w[d] + b[d];
}

// ---------------- tensor-core split-bf16 GEMM (near-fp32 accurate) --------
// C[M,N] = act(A[M,K] @ W[N,K]^T + bias)
// mode: 0 = store, 1 = +=, 2 = permuted += (row l*16+n -> n*128+l)
// mode 3 = in_proj special (BM=128 only): n0<DI -> fused causal conv+silu -> uout;
//          n0>=DI -> store to zout (compact DI-wide).
#define TBN 64
#define TBK 16
#define SW 12           // padded words per row (8 data + 4 pad)
template<int BM>
__global__ void __launch_bounds__(BM*2)
k_gemm_tc(const float* __restrict__ A, int lda,
          const float* __restrict__ W, int ldw,
          const float* __restrict__ bias,
          float* __restrict__ C, int ldc,
          int M, int N, int K, int act, int mode,
          const float* __restrict__ cvw, const float* __restrict__ cvb,
          float* __restrict__ uout, float* __restrict__ zout) {
    constexpr int T = BM*2;                  // 256 or 128 threads
    // smem words: Ash 2*BM*SW, Asl 2*BM*SW, Wsh 2*TBN*SW, Wsl 2*TBN*SW
    constexpr int AW = 2*BM*SW;
    constexpr int WW = 2*TBN*SW;
    __shared__ __align__(16) uint32_t smem[2*AW + 2*WW];
    uint32_t* Ash = smem;
    uint32_t* Asl = smem + AW;
    uint32_t* Wsh = smem + 2*AW;
    uint32_t* Wsl = smem + 2*AW + WW;
    #define ASH(s,m,k) Ash[((s)*BM+(m))*SW+(k)]
    #define ASL(s,m,k) Asl[((s)*BM+(m))*SW+(k)]
    #define WSH(s,n,k) Wsh[((s)*TBN+(n))*SW+(k)]
    #define WSL(s,n,k) Wsl[((s)*TBN+(n))*SW+(k)]

    int tid = threadIdx.x;
    int wid = tid >> 5, lane = tid & 31;
    int wm = wid >> 1, wn = wid & 1;    // BM=128: 4x2 warps; BM=64: 2x2 warps
    int g = lane >> 2, t = lane & 3;
    int m0 = blockIdx.y * BM, n0 = blockIdx.x * TBN;
    float acc[2][4][4] = {};

    constexpr int NA4 = BM*4/T;   // per-thread A float4 count (=2)
    constexpr int NW4 = TBN*4/T;  // per-thread W float4 count (1 or 2)
    float4 rA[NA4], rW[NW4 ? NW4 : 1];

    auto load_tile = [&](int k0) {
        #pragma unroll
        for (int i = 0; i < NA4; i++) {
            int slot = tid + i*T;
            int gm = m0 + (slot >> 2), gk = k0 + (slot & 3)*4;
            float4 v = make_float4(0.f,0.f,0.f,0.f);
            if (gm < M && gk < K) {
                if (gk + 3 < K) v = *reinterpret_cast<const float4*>(&A[(size_t)gm*lda + gk]);
                else {
                    v.x = A[(size_t)gm*lda+gk];
                    if (gk+1 < K) v.y = A[(size_t)gm*lda+gk+1];
                    if (gk+2 < K) v.z = A[(size_t)gm*lda+gk+2];
                }
            }
            rA[i] = v;
        }
        #pragma unroll
        for (int i = 0; i < NW4; i++) {
            int slot = tid + i*T;
            int gn = n0 + (slot >> 2), gk = k0 + (slot & 3)*4;
            float4 v = make_float4(0.f,0.f,0.f,0.f);
            if (gn < N && gk < K) {
                if (gk + 3 < K) v = *reinterpret_cast<const float4*>(&W[(size_t)gn*ldw + gk]);
                else {
                    v.x = W[(size_t)gn*ldw+gk];
                    if (gk+1 < K) v.y = W[(size_t)gn*ldw+gk+1];
                    if (gk+2 < K) v.z = W[(size_t)gn*ldw+gk+2];
                }
            }
            rW[i] = v;
        }
    };
    auto store_tile = [&](int s) {
        #pragma unroll
        for (int i = 0; i < NA4; i++) {
            int slot = tid + i*T;
            int m = slot >> 2, kw = (slot & 3)*2;
            float4 v = rA[i];
            uint32_t h0 = packbf(v.x, v.y), h1 = packbf(v.z, v.w);
            __nv_bfloat162 b0 = *reinterpret_cast<__nv_bfloat162*>(&h0);
            __nv_bfloat162 b1 = *reinterpret_cast<__nv_bfloat162*>(&h1);
            ASH(s,m,kw)   = h0; ASH(s,m,kw+1) = h1;
            ASL(s,m,kw)   = packbf(v.x - __low2float(b0), v.y - __high2float(b0));
            ASL(s,m,kw+1) = packbf(v.z - __low2float(b1), v.w - __high2float(b1));
        }
        #pragma unroll
        for (int i = 0; i < NW4; i++) {
            int slot = tid + i*T;
            int n = slot >> 2, kw = (slot & 3)*2;
            float4 v = rW[i];
            uint32_t h0 = packbf(v.x, v.y), h1 = packbf(v.z, v.w);
            __nv_bfloat162 b0 = *reinterpret_cast<__nv_bfloat162*>(&h0);
            __nv_bfloat162 b1 = *reinterpret_cast<__nv_bfloat162*>(&h1);
            WSH(s,n,kw)   = h0; WSH(s,n,kw+1) = h1;
            WSL(s,n,kw)   = packbf(v.x - __low2float(b0), v.y - __high2float(b0));
            WSL(s,n,kw+1) = packbf(v.z - __low2float(b1), v.w - __high2float(b1));
        }
    };

    int nt = (K + TBK - 1) / TBK;
    load_tile(0);
    store_tile(0);
    __syncthreads();

    for (int it = 0; it < nt; it++) {
        int cur = it & 1;
        if (it + 1 < nt) load_tile((it+1) * TBK);
        uint32_t ah[2][4], al[2][4], bh[4][2], bl[4][2];
        #pragma unroll
        for (int mf = 0; mf < 2; mf++) {
            int mr = wm*32 + mf*16;
            ah[mf][0] = ASH(cur, mr + g,     t    );
            ah[mf][1] = ASH(cur, mr + 8 + g, t    );
            ah[mf][2] = ASH(cur, mr + g,     t + 4);
            ah[mf][3] = ASH(cur, mr + 8 + g, t + 4);
            al[mf][0] = ASL(cur, mr + g,     t    );
            al[mf][1] = ASL(cur, mr + 8 + g, t    );
            al[mf][2] = ASL(cur, mr + g,     t + 4);
            al[mf][3] = ASL(cur, mr + 8 + g, t + 4);
        }
        #pragma unroll
        for (int nf = 0; nf < 4; nf++) {
            int nr = wn*32 + nf*8;
            bh[nf][0] = WSH(cur, nr + g, t    );
            bh[nf][1] = WSH(cur, nr + g, t + 4);
            bl[nf][0] = WSL(cur, nr + g, t    );
            bl[nf][1] = WSL(cur, nr + g, t + 4);
        }
        #pragma unroll
        for (int mf = 0; mf < 2; mf++)
            #pragma unroll
            for (int nf = 0; nf < 4; nf++) {
                mma16(acc[mf][nf], al[mf], bh[nf]);   // lo*hi
                mma16(acc[mf][nf], ah[mf], bl[nf]);   // hi*lo
                mma16(acc[mf][nf], ah[mf], bh[nf]);   // hi*hi
            }
        if (it + 1 < nt) store_tile(cur ^ 1);
        __syncthreads();
    }

    // ---- epilogue ----
    if (mode == 3 && n0 < DI) {
        // fused causal depthwise conv + silu (BM must be 128: full sequence in tile)
        float* cb = reinterpret_cast<float*>(smem);   // [128][68] reuse
        #pragma unroll
        for (int mf = 0; mf < 2; mf++)
            #pragma unroll
            for (int nf = 0; nf < 4; nf++)
                #pragma unroll
                for (int e = 0; e < 4; e++) {
                    int r = wm*32 + mf*16 + g + (e >> 1) * 8;
                    int c = wn*32 + nf*8 + 2*t + (e & 1);
                    cb[r*68 + c] = acc[mf][nf][e];
                }
        __syncthreads();
        int b = blockIdx.y;   // replica
        for (int idx = tid; idx < 128*TBN; idx += T) {
            int tt = idx >> 6, c = idx & 63;
            int ch = n0 + c;
            float s = cvb[ch];
            #pragma unroll
            for (int k = 0; k < DC; k++) {
                int tp = tt - (DC-1) + k;
                if (tp >= 0) s += cb[tp*68 + c] * cvw[ch*DC + k];
            }
            uout[(size_t)((b<<7)+tt)*DI + ch] = siluf(s);
        }
        return;
    }
    #pragma unroll
    for (int mf = 0; mf < 2; mf++) {
        #pragma unroll
        for (int nf = 0; nf < 4; nf++) {
            #pragma unroll
            for (int e = 0; e < 4; e++) {
                int gm = m0 + wm*32 + mf*16 + g + (e >> 1) * 8;
                int gn = n0 + wn*32 + nf*8 + 2*t + (e & 1);
                if (gm < M && gn < N) {
                    float v = acc[mf][nf][e];
                    if (bias) v += bias[gn];
                    if (act == 1) v = (v > 20.f) ? v : log1pf(__expf(v));
                    if (mode == 0)      C[(size_t)gm*ldc + gn] = v;
                    else if (mode == 1) C[(size_t)gm*ldc + gn] += v;
                    else if (mode == 2) {
                        int l = gm >> 4, n = gm & 15;
                        C[(size_t)((n<<7)+l)*ldc + gn] += v;
                    } else {            // mode 3, z half
                        zout[(size_t)gm*DI + (gn - DI)] = v;
                    }
                }
            }
        }
    }
}

// selective scan + fused gate. grid (DI/32, NREP), block 512: tid = s + 16*dl
__global__ void k_scan2(const float* __restrict__ A_log, const float* __restrict__ skipD) {
    __shared__ float sdt[LSEQ][32];  // recycled as y buffer
    __shared__ float su [LSEQ][32];
    __shared__ float sB [LSEQ][DS];
    __shared__ float sC [LSEQ][DS];
    int b = blockIdx.y, dchunk = blockIdx.x;
    int tid = threadIdx.x;
    for (int idx = tid; idx < LSEQ*32; idx += 512) {
        int tt = idx >> 5, dd = idx & 31;
        int row = (b<<7) + tt;
        sdt[tt][dd] = g_dt[(size_t)row*DI + dchunk*32 + dd];
        su [tt][dd] = g_u [(size_t)row*DI + dchunk*32 + dd];
    }
    for (int idx = tid; idx < LSEQ*DS; idx += 512) {
        int tt = idx >> 4, ss = idx & 15;
        int row = (b<<7) + tt;
        sB[tt][ss] = g_xdbl[(size_t)row*48 + DTR + ss];
        sC[tt][ss] = g_xdbl[(size_t)row*48 + DTR + DS + ss];
    }
    __syncthreads();
    int s = tid & 15, dl = tid >> 4;         // dl 0..31
    int d = dchunk*32 + dl;
    float Ads = -__expf(A_log[d*DS + s]);
    float skip = skipD[d];
    float h = 0.f;
    for (int t = 0; t < LSEQ; t++) {
        float dtv = sdt[t][dl], uv = su[t][dl];
        h = __expf(dtv*Ads)*h + dtv*uv*sB[t][s];
        float p = h * sC[t][s];
        p += __shfl_xor_sync(0xffffffffu, p, 8, 16);
        p += __shfl_xor_sync(0xffffffffu, p, 4, 16);
        p += __shfl_xor_sync(0xffffffffu, p, 2, 16);
        p += __shfl_xor_sync(0xffffffffu, p, 1, 16);
        if (s == 0) sdt[t][dl] = p + uv * skip;
    }
    __syncthreads();
    for (int idx = tid; idx < LSEQ*32; idx += 512) {
        int tt = idx >> 5, dd = idx & 31;
        int row = (b<<7) + tt;
        int gd = dchunk*32 + dd;
        float z = g_z[(size_t)row*DI + gd];
        g_gate[(size_t)row*DI + gd] = sdt[tt][dd] * siluf(z);
    }
}

// attention over the 16 replicas at each position l. grid=128, block=256.
__global__ void k_attn() {
    __shared__ float sK[NREP][DMODEL];
    __shared__ float sV[NREP][DMODEL];
    __shared__ float sS[NH][NREP][NREP];
    int l = blockIdx.x;
    int tid = threadIdx.x;
    for (int idx = tid; idx < NREP*DMODEL; idx += 256) {
        int n = idx >> 8, d = idx & (DMODEL-1);
        size_t base = (size_t)((l<<4)+n)*(3*DMODEL);
        sK[n][d] = g_qkv[base + DMODEL + d];
        sV[n][d] = g_qkv[base + 2*DMODEL + d];
    }
    __syncthreads();
    for (int idx = tid; idx < NH*NREP*NREP; idx += 256) {
        int h = idx >> 8;
        int i = (idx >> 4) & 15;
        int j = idx & 15;
        const float* q = &g_qkv[(size_t)((l<<4)+i)*(3*DMODEL) + h*HD];
        float dot = 0.f;
        #pragma unroll 8
        for (int dh = 0; dh < HD; dh++) dot += q[dh] * sK[j][h*HD + dh];
        sS[h][i][j] = dot * 0.125f;
    }
    __syncthreads();
    if (tid < NH*NREP) {
        int h = tid >> 4, i = tid & 15;
        float mx = -1e30f;
        #pragma unroll
        for (int j = 0; j < NREP; j++) mx = fmaxf(mx, sS[h][i][j]);
        float sum = 0.f;
        #pragma unroll
        for (int j = 0; j < NREP; j++) { float e = __expf(sS[h][i][j]-mx); sS[h][i][j] = e; sum += e; }
        float inv = 1.f/sum;
        #pragma unroll
        for (int j = 0; j < NREP; j++) sS[h][i][j] *= inv;
    }
    __syncthreads();
    for (int idx = tid; idx < NREP*DMODEL; idx += 256) {
        int i = idx >> 8, d = idx & (DMODEL-1);
        int h = d >> 6;
        float o = 0.f;
        #pragma unroll
        for (int j = 0; j < NREP; j++) o += sS[h][i][j] * sV[j][d];
        g_attno[(size_t)((l<<4)+i)*DMODEL + d] = o;
    }
}

// ---------------- launch ----------
extern "C" void kernel_launch(void* const* d_in, const int* in_sizes, int n_in,
                              void* d_out, int out_size) {
    const int*   x     = (const int*)  d_in[0];
    const float* emb   = (const float*)d_in[1];
    const float* n1w   = (const float*)d_in[2];
    const float* n1b   = (const float*)d_in[3];
    const float* n2w   = (const float*)d_in[4];
    const float* n2b   = (const float*)d_in[5];
    const float* ipw   = (const float*)d_in[6];
    const float* cw    = (const float*)d_in[7];
    const float* cb    = (const float*)d_in[8];
    const float* xpw   = (const float*)d_in[9];
    const float* dpw   = (const float*)d_in[10];
    const float* dpb   = (const float*)d_in[11];
    const float* alog  = (const float*)d_in[12];
    const float* dskip = (const float*)d_in[13];
    const float* opw   = (const float*)d_in[14];
    const float* aiw   = (const float*)d_in[15];
    const float* aib   = (const float*)d_in[16];
    const float* aow   = (const float*)d_in[17];
    const float* aob   = (const float*)d_in[18];
    const float* nfw   = (const float*)d_in[19];
    const float* nfb   = (const float*)d_in[20];
    const float* headb = (const float*)d_in[21];
    float* out = (float*)d_out;

    float* ph;    cudaGetSymbolAddress((void**)&ph, g_h);
    float* pxn;   cudaGetSymbolAddress((void**)&pxn, g_xn);
    float* pz;    cudaGetSymbolAddress((void**)&pz, g_z);
    float* pu;    cudaGetSymbolAddress((void**)&pu, g_u);
    float* pxdbl; cudaGetSymbolAddress((void**)&pxdbl, g_xdbl);
    float* pdt;   cudaGetSymbolAddress((void**)&pdt, g_dt);
    float* pgate; cudaGetSymbolAddress((void**)&pgate, g_gate);
    float* pxc;   cudaGetSymbolAddress((void**)&pxc, g_xc);
    float* pqkv;  cudaGetSymbolAddress((void**)&pqkv, g_qkv);
    float* pattno;cudaGetSymbolAddress((void**)&pattno, g_attno);
    float* phf;   cudaGetSymbolAddress((void**)&phf, g_hf);

    k_embed<<<(ROWS*DMODEL+255)/256, 256>>>(x, emb);

    for (int i = 0; i < NLAYER; i++) {
        const float* L_n1w = n1w + i*DMODEL;
        const float* L_n1b = n1b + i*DMODEL;
        const float* L_n2w = n2w + i*DMODEL;
        const float* L_n2b = n2b + i*DMODEL;
        const float* L_ipw = ipw + (size_t)i*2*DI*DMODEL;
        const float* L_cw  = cw  + (size_t)i*DI*DC;
        const float* L_cb  = cb  + (size_t)i*DI;
        const float* L_xpw = xpw + (size_t)i*(DTR+2*DS)*DI;
        const float* L_dpw = dpw + (size_t)i*DI*DTR;
        const float* L_dpb = dpb + (size_t)i*DI;
        const float* L_alog= alog+ (size_t)i*DI*DS;
        const float* L_skip= dskip+(size_t)i*DI;
        const float* L_opw = opw + (size_t)i*DMODEL*DI;
        const float* L_aiw = aiw + (size_t)i*3*DMODEL*DMODEL;
        const float* L_aib = aib + (size_t)i*3*DMODEL;
        const float* L_aow = aow + (size_t)i*DMODEL*DMODEL;
        const float* L_aob = aob + (size_t)i*DMODEL;

        // --- mamba branch ---
        k_ln<<<ROWS, 256>>>(ph, L_n1w, L_n1b, pxn, 0);
        // in_proj + fused conv+silu (u) / z store
        k_gemm_tc<128><<<dim3((2*DI)/TBN, ROWS/128), 256>>>(
            pxn, DMODEL, L_ipw, DMODEL, nullptr, nullptr, 0,
            ROWS, 2*DI, DMODEL, 0, 3, L_cw, L_cb, pu, pz);
        // xdbl = u @ xpw^T : [2048,48]
        k_gemm_tc<64><<<dim3(1, ROWS/64), 128>>>(
            pu, DI, L_xpw, DI, nullptr, pxdbl, DTR+2*DS,
            ROWS, DTR+2*DS, DI, 0, 0, nullptr, nullptr, nullptr, nullptr);
        // dt = softplus(xdbl[:, :16] @ dpw^T + dpb)
        k_gemm_tc<64><<<dim3(DI/TBN, ROWS/64), 128>>>(
            pxdbl, DTR+2*DS, L_dpw, DTR, L_dpb, pdt, DI,
            ROWS, DI, DTR, 1, 0, nullptr, nullptr, nullptr, nullptr);
        k_scan2<<<dim3(DI/32, NREP), 512>>>(L_alog, L_skip);
        // h += gate @ opw^T
        k_gemm_tc<64><<<dim3(DMODEL/TBN, ROWS/64), 128>>>(
            pgate, DI, L_opw, DI, nullptr, ph, DMODEL,
            ROWS, DMODEL, DI, 0, 1, nullptr, nullptr, nullptr, nullptr);
        // --- attention branch ---
        k_ln<<<ROWS, 256>>>(ph, L_n2w, L_n2b, pxc, 1);
        k_gemm_tc<128><<<dim3((3*DMODEL)/TBN, ROWS/128), 256>>>(
            pxc, DMODEL, L_aiw, DMODEL, L_aib, pqkv, 3*DMODEL,
            ROWS, 3*DMODEL, DMODEL, 0, 0, nullptr, nullptr, nullptr, nullptr);
        k_attn<<<LSEQ, 256>>>();
        k_gemm_tc<64><<<dim3(DMODEL/TBN, ROWS/64), 128>>>(
            pattno, DMODEL, L_aow, DMODEL, L_aob, ph, DMODEL,
            ROWS, DMODEL, DMODEL, 0, 2, nullptr, nullptr, nullptr, nullptr);
    }

    k_meanln<<<LSEQ, 256>>>(nfw, nfb);
    k_gemm_tc<128><<<dim3(VOCAB/TBN, 1), 256>>>(
        phf, DMODEL, emb, DMODEL, headb, out, VOCAB,
        LSEQ, VOCAB, DMODEL, 0, 0, nullptr, nullptr, nullptr, nullptr);
}